// round 1
// baseline (speedup 1.0000x reference)
#include <cuda_runtime.h>
#include <math.h>

// NetVLAD fused kernel, fp32 SIMT baseline.
// Shapes (fixed by the problem):
//   x:        [N=64, D=128, H=60, W=80]  -> P = 4800 pixels
//   conv_w:   [K=64, D=128]
//   centroids:[K=64, D=128]
//   out:      [N, K*D] = [64, 8192]

#define Nn 64
#define Dd 128
#define Pp 4800
#define Kk 64
#define TP 64          // pixels per tile
#define SPLIT 8        // CTAs per batch along P
#define NTILES (Pp/TP) // 75

#define WS_STRIDE 130  // ws[k][d] row stride (pad)
#define XS_STRIDE 66   // xs[d][p] row stride (pad, odd-pair -> conflict-free cols)
#define LS_STRIDE 66   // ls[k][p] row stride

#define SMEM_FLOATS (Kk*WS_STRIDE + Dd*XS_STRIDE + Kk*LS_STRIDE)

__device__ float g_agg[Nn * Kk * Dd];   // per-(n,k,d) aggregation scratch
__device__ float g_ssum[Nn * Kk];       // per-(n,k) soft-assign sums

// ---------------------------------------------------------------------------
// Kernel 1: zero the scratch buffers (graph replays need fresh zeros)
// ---------------------------------------------------------------------------
__global__ void netvlad_zero_kernel() {
    int idx = blockIdx.x * blockDim.x + threadIdx.x;
    int stride = gridDim.x * blockDim.x;
    for (int i = idx; i < Nn * Kk * Dd; i += stride) g_agg[i] = 0.f;
    for (int i = idx; i < Nn * Kk; i += stride)      g_ssum[i] = 0.f;
}

// ---------------------------------------------------------------------------
// Kernel 2: fused normalize + logits GEMM + softmax + aggregation GEMM
// grid = (SPLIT, N), block = 256 threads
// ---------------------------------------------------------------------------
__global__ __launch_bounds__(256, 2)
void netvlad_main_kernel(const float* __restrict__ x,
                         const float* __restrict__ w) {
    extern __shared__ float sh[];
    float* ws = sh;                       // [Kk][WS_STRIDE]
    float* xs = ws + Kk * WS_STRIDE;      // [Dd][XS_STRIDE]
    float* ls = xs + Dd * XS_STRIDE;      // [Kk][LS_STRIDE]

    const int tid = threadIdx.x;
    const int n   = blockIdx.y;
    const int s   = blockIdx.x;

    // stage conv_w into shared (once per CTA)
    for (int i = tid; i < Kk * Dd; i += 256) {
        int k = i >> 7, d = i & 127;
        ws[k * WS_STRIDE + d] = w[i];
    }

    const int tk = tid >> 4;      // 0..15
    const int tp = tid & 15;      // 0..15 (also used as td in agg gemm)
    const int pix = tid >> 2;     // 0..63
    const int sub = tid & 3;      // 0..3

    // persistent aggregation accumulators: k = tk+16i, d = tp+16j
    float acc[4][8];
#pragma unroll
    for (int i = 0; i < 4; i++)
#pragma unroll
        for (int j = 0; j < 8; j++) acc[i][j] = 0.f;
    float ssum_acc = 0.f;  // valid when tid < Kk

    const float* xn = x + (size_t)n * Dd * Pp;

    for (int t = s; t < NTILES; t += SPLIT) {
        const int p0 = t * TP;
        __syncthreads();  // protect xs/ls from previous iteration readers

        // --- load x tile [Dd][TP] (float4 global, float2 shared stores) ---
#pragma unroll
        for (int j = 0; j < 8; j++) {
            int idx4 = tid + 256 * j;            // 0..2047
            int d  = idx4 >> 4;
            int p4 = (idx4 & 15) << 2;
            float4 v = *reinterpret_cast<const float4*>(xn + d * Pp + p0 + p4);
            float* dst = &xs[d * XS_STRIDE + p4];
            *reinterpret_cast<float2*>(dst)     = make_float2(v.x, v.y);
            *reinterpret_cast<float2*>(dst + 2) = make_float2(v.z, v.w);
        }
        __syncthreads();

        // --- per-pixel L2 normalization over D (4 threads per pixel) ---
        {
            float ssq = 0.f;
#pragma unroll
            for (int i = 0; i < 32; i++) {
                float v = xs[(sub + 4 * i) * XS_STRIDE + pix];
                ssq += v * v;
            }
            ssq += __shfl_xor_sync(0xffffffffu, ssq, 1);
            ssq += __shfl_xor_sync(0xffffffffu, ssq, 2);
            float rin = 1.f / fmaxf(sqrtf(ssq), 1e-12f);
#pragma unroll
            for (int i = 0; i < 32; i++)
                xs[(sub + 4 * i) * XS_STRIDE + pix] *= rin;
        }
        __syncthreads();

        // --- logits GEMM: ls[k][p] = sum_d ws[k][d]*xs[d][p] ---
        // thread computes k = tk+16i (i<4), p = tp+16j (j<4)
        {
            float la[4][4];
#pragma unroll
            for (int i = 0; i < 4; i++)
#pragma unroll
                for (int j = 0; j < 4; j++) la[i][j] = 0.f;

            for (int d = 0; d < Dd; d++) {
                float a[4], b[4];
#pragma unroll
                for (int i = 0; i < 4; i++) a[i] = ws[(tk + 16 * i) * WS_STRIDE + d];
#pragma unroll
                for (int j = 0; j < 4; j++) b[j] = xs[d * XS_STRIDE + tp + 16 * j];
#pragma unroll
                for (int i = 0; i < 4; i++)
#pragma unroll
                    for (int j = 0; j < 4; j++) la[i][j] += a[i] * b[j];
            }
#pragma unroll
            for (int i = 0; i < 4; i++)
#pragma unroll
                for (int j = 0; j < 4; j++)
                    ls[(tk + 16 * i) * LS_STRIDE + tp + 16 * j] = la[i][j];
        }
        __syncthreads();

        // --- softmax over k per pixel (4 threads per pixel) ---
        {
            float m = -1e30f;
#pragma unroll
            for (int i = 0; i < 16; i++)
                m = fmaxf(m, ls[(sub + 4 * i) * LS_STRIDE + pix]);
            m = fmaxf(m, __shfl_xor_sync(0xffffffffu, m, 1));
            m = fmaxf(m, __shfl_xor_sync(0xffffffffu, m, 2));
            float e[16];
            float se = 0.f;
#pragma unroll
            for (int i = 0; i < 16; i++) {
                e[i] = __expf(ls[(sub + 4 * i) * LS_STRIDE + pix] - m);
                se += e[i];
            }
            se += __shfl_xor_sync(0xffffffffu, se, 1);
            se += __shfl_xor_sync(0xffffffffu, se, 2);
            float rs = 1.f / se;
#pragma unroll
            for (int i = 0; i < 16; i++)
                ls[(sub + 4 * i) * LS_STRIDE + pix] = e[i] * rs;
        }
        __syncthreads();

        // --- per-k soft-assign sum over this tile ---
        if (tid < Kk) {
            float ssl = 0.f;
#pragma unroll 8
            for (int p = 0; p < TP; p++) ssl += ls[tid * LS_STRIDE + p];
            ssum_acc += ssl;
        }

        // --- aggregation GEMM: acc[k][d] += sum_p sa[k][p]*xs[d][p] ---
        // thread: k = tk+16i (i<4), d = tp+16j (j<8)
        for (int p = 0; p < TP; p++) {
            float a[4], b[8];
#pragma unroll
            for (int i = 0; i < 4; i++) a[i] = ls[(tk + 16 * i) * LS_STRIDE + p];
#pragma unroll
            for (int j = 0; j < 8; j++) b[j] = xs[(tp + 16 * j) * XS_STRIDE + p];
#pragma unroll
            for (int i = 0; i < 4; i++)
#pragma unroll
                for (int j = 0; j < 8; j++) acc[i][j] += a[i] * b[j];
        }
    }

    // --- merge partials ---
#pragma unroll
    for (int i = 0; i < 4; i++) {
        int k = tk + 16 * i;
#pragma unroll
        for (int j = 0; j < 8; j++) {
            int d = tp + 16 * j;
            atomicAdd(&g_agg[((size_t)n * Kk + k) * Dd + d], acc[i][j]);
        }
    }
    if (tid < Kk) atomicAdd(&g_ssum[n * Kk + tid], ssum_acc);
}

// ---------------------------------------------------------------------------
// Kernel 3: vlad = agg - ssum*centroid, intra L2 norm, global L2 norm
// grid = N, block = 256 (4 threads per k-row)
// ---------------------------------------------------------------------------
__global__ __launch_bounds__(256)
void netvlad_finalize_kernel(const float* __restrict__ cent,
                             float* __restrict__ out) {
    __shared__ float sred[256];
    const int n   = blockIdx.x;
    const int tid = threadIdx.x;
    const int k   = tid >> 2;
    const int sub = tid & 3;
    const int dbase = sub * 32;

    float v[32];
    const float ssk = g_ssum[n * Kk + k];
    const float* ap = &g_agg[((size_t)n * Kk + k) * Dd + dbase];
    const float* cp = &cent[k * Dd + dbase];

    float ssq = 0.f;
#pragma unroll
    for (int q = 0; q < 8; q++) {
        float4 a = *reinterpret_cast<const float4*>(ap + 4 * q);
        float4 c = *reinterpret_cast<const float4*>(cp + 4 * q);
        float v0 = a.x - ssk * c.x;
        float v1 = a.y - ssk * c.y;
        float v2 = a.z - ssk * c.z;
        float v3 = a.w - ssk * c.w;
        v[4 * q + 0] = v0; v[4 * q + 1] = v1;
        v[4 * q + 2] = v2; v[4 * q + 3] = v3;
        ssq += v0 * v0 + v1 * v1 + v2 * v2 + v3 * v3;
    }
    ssq += __shfl_xor_sync(0xffffffffu, ssq, 1);
    ssq += __shfl_xor_sync(0xffffffffu, ssq, 2);
    const float rin = 1.f / fmaxf(sqrtf(ssq), 1e-12f);

    // contribution of this (normalized) row to the global sum of squares
    sred[tid] = (sub == 0) ? ssq * rin * rin : 0.f;
    __syncthreads();
    for (int st = 128; st > 0; st >>= 1) {
        if (tid < st) sred[tid] += sred[tid + st];
        __syncthreads();
    }
    const float rg = 1.f / fmaxf(sqrtf(sred[0]), 1e-12f);
    const float sc = rin * rg;

    float* op = out + (size_t)n * Kk * Dd + k * Dd + dbase;
#pragma unroll
    for (int q = 0; q < 8; q++) {
        float4 o;
        o.x = v[4 * q + 0] * sc;
        o.y = v[4 * q + 1] * sc;
        o.z = v[4 * q + 2] * sc;
        o.w = v[4 * q + 3] * sc;
        *reinterpret_cast<float4*>(op + 4 * q) = o;
    }
}

// ---------------------------------------------------------------------------
extern "C" void kernel_launch(void* const* d_in, const int* in_sizes, int n_in,
                              void* d_out, int out_size) {
    const float* x    = (const float*)d_in[0];
    const float* w    = (const float*)d_in[1];
    const float* cent = (const float*)d_in[2];
    float* out = (float*)d_out;

    const size_t smem = (size_t)SMEM_FLOATS * sizeof(float);  // ~84 KB
    cudaFuncSetAttribute(netvlad_main_kernel,
                         cudaFuncAttributeMaxDynamicSharedMemorySize, (int)smem);

    netvlad_zero_kernel<<<1032, 512>>>();
    netvlad_main_kernel<<<dim3(SPLIT, Nn), 256, smem>>>(x, w);
    netvlad_finalize_kernel<<<Nn, 256>>>(cent, out);
}

// round 2
// speedup vs baseline: 1.1383x; 1.1383x over previous
#include <cuda_runtime.h>
#include <math.h>

// NetVLAD fused kernel, fp32 SIMT + packed FFMA2 (fma.rn.f32x2).
// Shapes: x [64,128,60,80] (P=4800), conv_w [64,128], centroids [64,128],
// out [64, 8192].

#define Nn 64
#define Dd 128
#define Pp 4800
#define Kk 64
#define TP 64          // pixels per tile
#define SPLIT 8        // CTAs per batch along P
#define NTILES (Pp/TP) // 75

#define WS_STRIDE 130  // ws[k][d]
#define XS_STRIDE 68   // xs[d][p]  (even + mult-of-4: LDS.64 pairs + float4)
#define LS_STRIDE 68   // ls[k][p]

#define SMEM_FLOATS (Kk*WS_STRIDE + Dd*XS_STRIDE + Kk*LS_STRIDE)

__device__ float g_agg[Nn * Kk * Dd];
__device__ float g_ssum[Nn * Kk];

// ---- packed f32x2 helpers ------------------------------------------------
typedef unsigned long long u64;

static __device__ __forceinline__ u64 fma2(u64 a, u64 b, u64 c) {
    u64 d;
    asm("fma.rn.f32x2 %0, %1, %2, %3;" : "=l"(d) : "l"(a), "l"(b), "l"(c));
    return d;
}
static __device__ __forceinline__ u64 dup2(float x) {
    u64 d;
    asm("mov.b64 %0, {%1, %1};" : "=l"(d) : "f"(x));
    return d;
}
static __device__ __forceinline__ float hadd2(u64 v) {
    float lo, hi;
    asm("mov.b64 {%0, %1}, %2;" : "=f"(lo), "=f"(hi) : "l"(v));
    return lo + hi;
}

// ---------------------------------------------------------------------------
// Kernel 1: zero scratch
// ---------------------------------------------------------------------------
__global__ void netvlad_zero_kernel() {
    int idx = blockIdx.x * blockDim.x + threadIdx.x;
    int stride = gridDim.x * blockDim.x;
    for (int i = idx; i < Nn * Kk * Dd; i += stride) g_agg[i] = 0.f;
    for (int i = idx; i < Nn * Kk; i += stride)      g_ssum[i] = 0.f;
}

// ---------------------------------------------------------------------------
// Kernel 2: fused normalize + logits GEMM + softmax + aggregation GEMM
// grid = (SPLIT, N), block = 256
// ---------------------------------------------------------------------------
__global__ __launch_bounds__(256, 2)
void netvlad_main_kernel(const float* __restrict__ x,
                         const float* __restrict__ w) {
    extern __shared__ float sh[];
    float* ws = sh;                       // [Kk][WS_STRIDE]
    float* xs = ws + Kk * WS_STRIDE;      // [Dd][XS_STRIDE]
    float* ls = xs + Dd * XS_STRIDE;      // [Kk][LS_STRIDE]

    const int tid = threadIdx.x;
    const int n   = blockIdx.y;
    const int s   = blockIdx.x;

    for (int i = tid; i < Kk * Dd; i += 256) {
        int k = i >> 7, d = i & 127;
        ws[k * WS_STRIDE + d] = w[i];
    }

    const int tk = tid >> 4;      // 0..15
    const int tp = tid & 15;      // 0..15
    const int pix = tid >> 2;     // 0..63
    const int sub = tid & 3;      // 0..3

    // agg accumulators: k = tk+16i, d = tp+16j; packed halves = even/odd p partials
    u64 acc2[4][8];
#pragma unroll
    for (int i = 0; i < 4; i++)
#pragma unroll
        for (int j = 0; j < 8; j++) acc2[i][j] = 0ull;
    float ssum_acc = 0.f;

    const float* xn = x + (size_t)n * Dd * Pp;

    for (int t = s; t < NTILES; t += SPLIT) {
        const int p0 = t * TP;
        __syncthreads();  // xs/ls consumed by previous iteration

        // --- load x tile [Dd][TP]: float4 global -> float4 shared ---
#pragma unroll
        for (int j = 0; j < 8; j++) {
            int idx4 = tid + 256 * j;            // 0..2047
            int d  = idx4 >> 4;
            int p4 = (idx4 & 15) << 2;
            float4 v = *reinterpret_cast<const float4*>(xn + d * Pp + p0 + p4);
            *reinterpret_cast<float4*>(&xs[d * XS_STRIDE + p4]) = v;
        }
        __syncthreads();

        // --- per-pixel L2 normalization over D (4 threads/pixel) ---
        {
            float ssq = 0.f;
#pragma unroll
            for (int i = 0; i < 32; i++) {
                float v = xs[(sub + 4 * i) * XS_STRIDE + pix];
                ssq += v * v;
            }
            ssq += __shfl_xor_sync(0xffffffffu, ssq, 1);
            ssq += __shfl_xor_sync(0xffffffffu, ssq, 2);
            float rin = 1.f / fmaxf(sqrtf(ssq), 1e-12f);
#pragma unroll
            for (int i = 0; i < 32; i++)
                xs[(sub + 4 * i) * XS_STRIDE + pix] *= rin;
        }
        __syncthreads();

        // --- logits GEMM: ls[k][p] = sum_d ws[k][d]*xs[d][p] ---
        // thread: k = tk+16i (i<4), p-pairs at 2*tp + 32*j (j<2), packed over p
        {
            u64 la2[4][2];
#pragma unroll
            for (int i = 0; i < 4; i++) { la2[i][0] = 0ull; la2[i][1] = 0ull; }

#pragma unroll 2
            for (int d = 0; d < Dd; d++) {
                u64 a[4], b[2];
#pragma unroll
                for (int i = 0; i < 4; i++)
                    a[i] = dup2(ws[(tk + 16 * i) * WS_STRIDE + d]);
#pragma unroll
                for (int j = 0; j < 2; j++)
                    b[j] = *reinterpret_cast<const u64*>(
                        &xs[d * XS_STRIDE + 2 * tp + 32 * j]);
#pragma unroll
                for (int i = 0; i < 4; i++)
#pragma unroll
                    for (int j = 0; j < 2; j++)
                        la2[i][j] = fma2(a[i], b[j], la2[i][j]);
            }
#pragma unroll
            for (int i = 0; i < 4; i++)
#pragma unroll
                for (int j = 0; j < 2; j++)
                    *reinterpret_cast<u64*>(
                        &ls[(tk + 16 * i) * LS_STRIDE + 2 * tp + 32 * j]) = la2[i][j];
        }
        __syncthreads();

        // --- softmax over k per pixel (4 threads/pixel) ---
        {
            float m = -1e30f;
#pragma unroll
            for (int i = 0; i < 16; i++)
                m = fmaxf(m, ls[(sub + 4 * i) * LS_STRIDE + pix]);
            m = fmaxf(m, __shfl_xor_sync(0xffffffffu, m, 1));
            m = fmaxf(m, __shfl_xor_sync(0xffffffffu, m, 2));
            float e[16];
            float se = 0.f;
#pragma unroll
            for (int i = 0; i < 16; i++) {
                e[i] = __expf(ls[(sub + 4 * i) * LS_STRIDE + pix] - m);
                se += e[i];
            }
            se += __shfl_xor_sync(0xffffffffu, se, 1);
            se += __shfl_xor_sync(0xffffffffu, se, 2);
            float rs = 1.f / se;
#pragma unroll
            for (int i = 0; i < 16; i++)
                ls[(sub + 4 * i) * LS_STRIDE + pix] = e[i] * rs;
        }
        __syncthreads();

        // --- per-k soft-assign sum over tile ---
        if (tid < Kk) {
            float ssl = 0.f;
#pragma unroll 8
            for (int p = 0; p < TP; p++) ssl += ls[tid * LS_STRIDE + p];
            ssum_acc += ssl;
        }

        // --- aggregation GEMM, packed over p-reduction (pure pair loads) ---
        // acc2[i][j] halves accumulate even/odd p; combined at epilogue.
#pragma unroll 2
        for (int p2 = 0; p2 < TP / 2; p2++) {
            u64 a[4], b[8];
#pragma unroll
            for (int i = 0; i < 4; i++)
                a[i] = *reinterpret_cast<const u64*>(
                    &ls[(tk + 16 * i) * LS_STRIDE + 2 * p2]);
#pragma unroll
            for (int j = 0; j < 8; j++)
                b[j] = *reinterpret_cast<const u64*>(
                    &xs[(tp + 16 * j) * XS_STRIDE + 2 * p2]);
#pragma unroll
            for (int i = 0; i < 4; i++)
#pragma unroll
                for (int j = 0; j < 8; j++)
                    acc2[i][j] = fma2(a[i], b[j], acc2[i][j]);
        }
    }

    // --- merge partials ---
#pragma unroll
    for (int i = 0; i < 4; i++) {
        int k = tk + 16 * i;
#pragma unroll
        for (int j = 0; j < 8; j++) {
            int d = tp + 16 * j;
            atomicAdd(&g_agg[((size_t)n * Kk + k) * Dd + d], hadd2(acc2[i][j]));
        }
    }
    if (tid < Kk) atomicAdd(&g_ssum[n * Kk + tid], ssum_acc);
}

// ---------------------------------------------------------------------------
// Kernel 3: vlad = agg - ssum*centroid, intra L2 norm, global L2 norm
// ---------------------------------------------------------------------------
__global__ __launch_bounds__(256)
void netvlad_finalize_kernel(const float* __restrict__ cent,
                             float* __restrict__ out) {
    __shared__ float sred[256];
    const int n   = blockIdx.x;
    const int tid = threadIdx.x;
    const int k   = tid >> 2;
    const int sub = tid & 3;
    const int dbase = sub * 32;

    float v[32];
    const float ssk = g_ssum[n * Kk + k];
    const float* ap = &g_agg[((size_t)n * Kk + k) * Dd + dbase];
    const float* cp = &cent[k * Dd + dbase];

    float ssq = 0.f;
#pragma unroll
    for (int q = 0; q < 8; q++) {
        float4 a = *reinterpret_cast<const float4*>(ap + 4 * q);
        float4 c = *reinterpret_cast<const float4*>(cp + 4 * q);
        float v0 = a.x - ssk * c.x;
        float v1 = a.y - ssk * c.y;
        float v2 = a.z - ssk * c.z;
        float v3 = a.w - ssk * c.w;
        v[4 * q + 0] = v0; v[4 * q + 1] = v1;
        v[4 * q + 2] = v2; v[4 * q + 3] = v3;
        ssq += v0 * v0 + v1 * v1 + v2 * v2 + v3 * v3;
    }
    ssq += __shfl_xor_sync(0xffffffffu, ssq, 1);
    ssq += __shfl_xor_sync(0xffffffffu, ssq, 2);
    const float rin = 1.f / fmaxf(sqrtf(ssq), 1e-12f);

    sred[tid] = (sub == 0) ? ssq * rin * rin : 0.f;
    __syncthreads();
    for (int st = 128; st > 0; st >>= 1) {
        if (tid < st) sred[tid] += sred[tid + st];
        __syncthreads();
    }
    const float rg = 1.f / fmaxf(sqrtf(sred[0]), 1e-12f);
    const float sc = rin * rg;

    float* op = out + (size_t)n * Kk * Dd + k * Dd + dbase;
#pragma unroll
    for (int q = 0; q < 8; q++) {
        float4 o;
        o.x = v[4 * q + 0] * sc;
        o.y = v[4 * q + 1] * sc;
        o.z = v[4 * q + 2] * sc;
        o.w = v[4 * q + 3] * sc;
        *reinterpret_cast<float4*>(op + 4 * q) = o;
    }
}

// ---------------------------------------------------------------------------
extern "C" void kernel_launch(void* const* d_in, const int* in_sizes, int n_in,
                              void* d_out, int out_size) {
    const float* x    = (const float*)d_in[0];
    const float* w    = (const float*)d_in[1];
    const float* cent = (const float*)d_in[2];
    float* out = (float*)d_out;

    const size_t smem = (size_t)SMEM_FLOATS * sizeof(float);
    cudaFuncSetAttribute(netvlad_main_kernel,
                         cudaFuncAttributeMaxDynamicSharedMemorySize, (int)smem);

    netvlad_zero_kernel<<<1032, 512>>>();
    netvlad_main_kernel<<<dim3(SPLIT, Nn), 256, smem>>>(x, w);
    netvlad_finalize_kernel<<<Nn, 256>>>(cent, out);
}